// round 1
// baseline (speedup 1.0000x reference)
#include <cuda_runtime.h>
#include <math.h>

// Problem constants
#define BI   4
#define LI   2048
#define DI   1024
#define HI   16
#define DKI  64

// Scratch (device globals: allocation-free per harness rules). ~201 MB total.
__device__ float g_Qh[(size_t)BI*HI*LI*DKI];   // [b][h][l][dk]
__device__ float g_Kh[(size_t)BI*HI*LI*DKI];   // [b][h][l][dk]
__device__ float g_Vh[(size_t)BI*HI*LI*DKI];   // [b][h][l][dv]
__device__ float g_Vt[(size_t)BI*HI*DKI*LI];   // [b][h][dv][l]  (transposed V)
__device__ float g_O [(size_t)BI*LI*DI];       // attn @ V, [b][l][h*dv]
__device__ float g_O2[(size_t)BI*LI*DI];       // out-proj result (pre-LN)

// ---------------- packed fp32x2 helpers (Blackwell f32x2 pipe) ----------------
__device__ __forceinline__ void fma2(unsigned long long& c, unsigned long long a,
                                     unsigned long long b) {
    asm("fma.rn.f32x2 %0, %1, %2, %3;" : "=l"(c) : "l"(a), "l"(b), "l"(c));
}
__device__ __forceinline__ unsigned long long rep2(float x) {
    unsigned long long r; unsigned u = __float_as_uint(x);
    asm("mov.b64 %0, {%1, %1};" : "=l"(r) : "r"(u));
    return r;
}
__device__ __forceinline__ void unpack2(unsigned long long c, float& lo, float& hi) {
    unsigned a, b;
    asm("mov.b64 {%0, %1}, %2;" : "=r"(a), "=r"(b) : "l"(c));
    lo = __uint_as_float(a); hi = __uint_as_float(b);
}

// ---------------------------------------------------------------------------
// Generic NT GEMM: C = A(MxK, row-major) * B(NxK, row-major)^T  [+ bias]
// MODE 0: QKV projection -> scatter to [b][h][l][dk], += bias[j]
// MODE 1: plain row-major C[M][N], += bias[j]
// MODE 2: scores (batched over z = b*H+h): val*scale, diag -> -inf,
//         written to attn_flat layout [h][b][l][m]
// MODE 3: attn@V (batched over z = b*H+h): write to g_O[b][l][h*64+dv]
// All dims assumed multiples of tile sizes (true for this problem).
// ---------------------------------------------------------------------------
template<int BM, int BN, int BK, int TM, int TN, int MODE>
__global__ void __launch_bounds__((BM/TM)*(BN/TN))
gemm_nt(const float* __restrict__ A, const float* __restrict__ B,
        float* __restrict__ C, const float* __restrict__ bias,
        int M, int N, int K, float scale)
{
    constexpr int NT = (BM/TM)*(BN/TN);
    __shared__ __align__(16) float As[BK][BM];
    __shared__ __align__(16) float Bs[BK][BN];

    const int tid = threadIdx.x;
    const int bc = blockIdx.x, br = blockIdx.y, z = blockIdx.z;

    const float* Ap = A;
    const float* Bp = B;
    if (MODE == 2) {
        Ap = A + (size_t)z * LI * DKI;          // Qh batch (b*H+h)
        Bp = B + (size_t)z * LI * DKI;          // Kh batch
    }
    if (MODE == 3) {
        int b = z / HI, h = z % HI;
        Ap = A + ((size_t)(h * BI + b)) * LI * LI;   // attn_flat [h][b]
        Bp = B + (size_t)z * DKI * LI;               // Vt batch
    }

    unsigned long long acc[TM][TN/2];
    #pragma unroll
    for (int i = 0; i < TM; i++)
        #pragma unroll
        for (int j = 0; j < TN/2; j++) acc[i][j] = 0ULL;

    const int trow = tid / (BN/TN);
    const int tcol = tid % (BN/TN);

    constexpr int AV4 = BM * BK / 4;
    constexpr int BV4 = BN * BK / 4;

    for (int k0 = 0; k0 < K; k0 += BK) {
        #pragma unroll
        for (int idx = tid; idx < AV4; idx += NT) {
            int r  = idx / (BK/4);
            int c4 = idx % (BK/4);
            float4 v = *(const float4*)(Ap + (size_t)(br*BM + r)*K + k0 + c4*4);
            As[c4*4+0][r] = v.x; As[c4*4+1][r] = v.y;
            As[c4*4+2][r] = v.z; As[c4*4+3][r] = v.w;
        }
        #pragma unroll
        for (int idx = tid; idx < BV4; idx += NT) {
            int r  = idx / (BK/4);
            int c4 = idx % (BK/4);
            float4 v = *(const float4*)(Bp + (size_t)(bc*BN + r)*K + k0 + c4*4);
            Bs[c4*4+0][r] = v.x; Bs[c4*4+1][r] = v.y;
            Bs[c4*4+2][r] = v.z; Bs[c4*4+3][r] = v.w;
        }
        __syncthreads();

        #pragma unroll
        for (int k = 0; k < BK; k++) {
            float a_frag[TM];
            #pragma unroll
            for (int i = 0; i < TM; i += 4) {
                float4 v = *(const float4*)&As[k][trow*TM + i];
                a_frag[i] = v.x; a_frag[i+1] = v.y; a_frag[i+2] = v.z; a_frag[i+3] = v.w;
            }
            unsigned long long b_frag[TN/2];
            #pragma unroll
            for (int j = 0; j < TN/2; j += 2) {
                ulonglong2 u = *(const ulonglong2*)&Bs[k][tcol*TN + j*2];
                b_frag[j] = u.x; b_frag[j+1] = u.y;
            }
            #pragma unroll
            for (int i = 0; i < TM; i++) {
                unsigned long long a2 = rep2(a_frag[i]);
                #pragma unroll
                for (int j = 0; j < TN/2; j++) fma2(acc[i][j], a2, b_frag[j]);
            }
        }
        __syncthreads();
    }

    // Epilogue
    #pragma unroll
    for (int i = 0; i < TM; i++) {
        int gi = br*BM + trow*TM + i;
        #pragma unroll
        for (int j = 0; j < TN/2; j++) {
            float lo, hi;
            unpack2(acc[i][j], lo, hi);
            int gj0 = bc*BN + tcol*TN + j*2;
            #pragma unroll
            for (int s = 0; s < 2; s++) {
                int gj = gj0 + s;
                float v = (s == 0) ? lo : hi;
                if (MODE == 0) {
                    int b = gi >> 11, l = gi & (LI-1);
                    int h = gj >> 6,  dk = gj & 63;
                    C[(((size_t)(b*HI + h)*LI + l) << 6) + dk] = v + bias[gj];
                } else if (MODE == 1) {
                    C[(size_t)gi * N + gj] = v + bias[gj];
                } else if (MODE == 2) {
                    int b = z / HI, h = z % HI;
                    float sv = v * scale;
                    if (gi == gj) sv = -INFINITY;
                    C[((size_t)(h*BI + b)*LI + gi)*LI + gj] = sv;
                } else { // MODE 3
                    int b = z / HI, h = z % HI;
                    C[((size_t)b*LI + gi)*DI + h*DKI + gj] = v;
                }
            }
        }
    }
}

// ---------------- V transpose: [b][h][l][dv] -> [b][h][dv][l] ----------------
__global__ void __launch_bounds__(256) transpose_v(const float* __restrict__ in,
                                                   float* __restrict__ out)
{
    __shared__ float t[32][33];
    int z  = blockIdx.z;                 // bh
    int l0 = blockIdx.y * 32;
    int d0 = blockIdx.x * 32;
    const float* ip = in  + (size_t)z * LI * DKI;
    float*       op = out + (size_t)z * DKI * LI;
    int x = threadIdx.x, y = threadIdx.y;   // 32 x 8
    #pragma unroll
    for (int i = 0; i < 32; i += 8)
        t[y + i][x] = ip[(size_t)(l0 + y + i) * DKI + d0 + x];
    __syncthreads();
    #pragma unroll
    for (int i = 0; i < 32; i += 8)
        op[(size_t)(d0 + y + i) * LI + l0 + x] = t[x][y + i];
}

// ---------------- reductions ----------------
__device__ __forceinline__ float warpMax(float v) {
    #pragma unroll
    for (int o = 16; o; o >>= 1) v = fmaxf(v, __shfl_xor_sync(0xffffffffu, v, o));
    return v;
}
__device__ __forceinline__ float warpSum(float v) {
    #pragma unroll
    for (int o = 16; o; o >>= 1) v += __shfl_xor_sync(0xffffffffu, v, o);
    return v;
}

// ---------------- row softmax in-place over attn [64*2048 rows x 2048] -------
__global__ void __launch_bounds__(256) softmax_kernel(float* __restrict__ attn)
{
    size_t row = blockIdx.x;
    float4* p = (float4*)(attn + row * LI);
    int t = threadIdx.x;
    float4 v0 = p[t];
    float4 v1 = p[t + 256];

    float m = fmaxf(fmaxf(fmaxf(v0.x, v0.y), fmaxf(v0.z, v0.w)),
                    fmaxf(fmaxf(v1.x, v1.y), fmaxf(v1.z, v1.w)));
    m = warpMax(m);
    __shared__ float red[8];
    if ((t & 31) == 0) red[t >> 5] = m;
    __syncthreads();
    m = red[0];
    #pragma unroll
    for (int i = 1; i < 8; i++) m = fmaxf(m, red[i]);

    v0.x = __expf(v0.x - m); v0.y = __expf(v0.y - m);
    v0.z = __expf(v0.z - m); v0.w = __expf(v0.w - m);
    v1.x = __expf(v1.x - m); v1.y = __expf(v1.y - m);
    v1.z = __expf(v1.z - m); v1.w = __expf(v1.w - m);

    float s = (v0.x + v0.y + v0.z + v0.w) + (v1.x + v1.y + v1.z + v1.w);
    s = warpSum(s);
    __syncthreads();
    if ((t & 31) == 0) red[t >> 5] = s;
    __syncthreads();
    s = red[0];
    #pragma unroll
    for (int i = 1; i < 8; i++) s += red[i];

    float inv = 1.0f / s;
    v0.x *= inv; v0.y *= inv; v0.z *= inv; v0.w *= inv;
    v1.x *= inv; v1.y *= inv; v1.z *= inv; v1.w *= inv;
    p[t] = v0;
    p[t + 256] = v1;
}

// ---------------- residual + LayerNorm (biased variance) ---------------------
__global__ void __launch_bounds__(256) ln_kernel(const float* __restrict__ o2,
                                                 const float* __restrict__ res,
                                                 const float* __restrict__ gamma,
                                                 const float* __restrict__ beta,
                                                 float* __restrict__ out)
{
    size_t row = blockIdx.x;
    int t = threadIdx.x;
    float4 a = ((const float4*)(o2  + row * DI))[t];
    float4 r = ((const float4*)(res + row * DI))[t];
    float x0 = a.x + r.x, x1 = a.y + r.y, x2 = a.z + r.z, x3 = a.w + r.w;
    float s  = x0 + x1 + x2 + x3;
    float sq = x0*x0 + x1*x1 + x2*x2 + x3*x3;
    s = warpSum(s); sq = warpSum(sq);
    __shared__ float rs[8], rq[8];
    if ((t & 31) == 0) { rs[t >> 5] = s; rq[t >> 5] = sq; }
    __syncthreads();
    s = 0.0f; sq = 0.0f;
    #pragma unroll
    for (int i = 0; i < 8; i++) { s += rs[i]; sq += rq[i]; }
    float mu   = s * (1.0f / DI);
    float var  = sq * (1.0f / DI) - mu * mu;
    float rstd = rsqrtf(var + 1e-5f);
    float4 g = ((const float4*)gamma)[t];
    float4 b = ((const float4*)beta)[t];
    float4 o;
    o.x = (x0 - mu) * rstd * g.x + b.x;
    o.y = (x1 - mu) * rstd * g.y + b.y;
    o.z = (x2 - mu) * rstd * g.z + b.z;
    o.w = (x3 - mu) * rstd * g.w + b.w;
    ((float4*)(out + row * DI))[t] = o;
}

// ---------------------------------------------------------------------------
extern "C" void kernel_launch(void* const* d_in, const int* in_sizes, int n_in,
                              void* d_out, int out_size)
{
    const float* q     = (const float*)d_in[0];
    const float* k     = (const float*)d_in[1];
    const float* v     = (const float*)d_in[2];
    const float* Wq    = (const float*)d_in[3];
    const float* bq    = (const float*)d_in[4];
    const float* Wk    = (const float*)d_in[5];
    const float* bk    = (const float*)d_in[6];
    const float* Wv    = (const float*)d_in[7];
    const float* bv    = (const float*)d_in[8];
    const float* Wo    = (const float*)d_in[9];
    const float* bo    = (const float*)d_in[10];
    const float* gamma = (const float*)d_in[11];
    const float* beta  = (const float*)d_in[12];

    float* out  = (float*)d_out;
    float* attn = out + (size_t)BI * LI * DI;   // attn_flat [h*B][L][L]

    float *pQh, *pKh, *pVh, *pVt, *pO, *pO2;
    cudaGetSymbolAddress((void**)&pQh, g_Qh);
    cudaGetSymbolAddress((void**)&pKh, g_Kh);
    cudaGetSymbolAddress((void**)&pVh, g_Vh);
    cudaGetSymbolAddress((void**)&pVt, g_Vt);
    cudaGetSymbolAddress((void**)&pO,  g_O);
    cudaGetSymbolAddress((void**)&pO2, g_O2);

    const int M = BI * LI;   // 8192

    // QKV projections -> [b][h][l][d]
    gemm_nt<128,128,16,8,8,0><<<dim3(DI/128, M/128, 1), 256>>>(q, Wq, pQh, bq, M, DI, DI, 0.f);
    gemm_nt<128,128,16,8,8,0><<<dim3(DI/128, M/128, 1), 256>>>(k, Wk, pKh, bk, M, DI, DI, 0.f);
    gemm_nt<128,128,16,8,8,0><<<dim3(DI/128, M/128, 1), 256>>>(v, Wv, pVh, bv, M, DI, DI, 0.f);

    // V transpose for NT attn@V
    transpose_v<<<dim3(DKI/32, LI/32, BI*HI), dim3(32, 8)>>>(pVh, pVt);

    // scores = scale * Q Kt, diag -> -inf, written to attn_flat layout
    gemm_nt<128,128,16,8,8,2><<<dim3(LI/128, LI/128, BI*HI), 256>>>(pQh, pKh, attn, nullptr,
                                                                    LI, LI, DKI, 0.125f);
    // row softmax in place
    softmax_kernel<<<BI*HI*LI, 256>>>(attn);

    // attn @ V -> g_O [b][l][h*dv]
    gemm_nt<128,64,16,8,8,3><<<dim3(1, LI/128, BI*HI), 128>>>(attn, pVt, pO, nullptr,
                                                              LI, DKI, LI, 0.f);
    // output projection
    gemm_nt<128,128,16,8,8,1><<<dim3(DI/128, M/128, 1), 256>>>(pO, Wo, pO2, bo, M, DI, DI, 0.f);

    // residual + LayerNorm -> out
    ln_kernel<<<M, 256>>>(pO2, q, gamma, beta, out);
}